// round 3
// baseline (speedup 1.0000x reference)
#include <cuda_runtime.h>

// Problem dims (fixed by the dataset): N=100000 nodes, F_in=512, HID=16,
// NCLS=40, E=3200000 directed edges (+N implicit self loops).
#define NMAX 100000
#define EMAX 3200000
#define FIN  512
#define HID  16
#define NCLS 40

// -------- device scratch (no allocations allowed) --------
// float4 arrays => 16B-aligned bases for LDG.128 / STG.128 / red.v4.
__device__ float4 g_h1[NMAX * HID / 4];    // h1, later z = relu(agg1+b1)
__device__ float4 g_agg1[NMAX * HID / 4];  // aggregation buffer (both layers)
__device__ float  g_dinv[NMAX];            // deg -> rsqrt(deg)
__device__ int    g_src[EMAX];
__device__ int    g_dst[EMAX];
__device__ int    g_fmt64;                 // 1 if edge_index is int64 on device

// ---------------------------------------------------------
// Detect edge_index element width. int64 little-endian values < 2^31 have
// all-zero high words; int32 random node ids essentially never do.
__global__ void k_detect_fmt(const unsigned int* __restrict__ w) {
    unsigned int acc = 0;
#pragma unroll
    for (int i = 0; i < 128; i++) acc |= w[2 * i + 1];
    g_fmt64 = (acc == 0u) ? 1 : 0;
}

__global__ void k_init_deg(int n) {
    int i = blockIdx.x * blockDim.x + threadIdx.x;
    if (i < n) g_dinv[i] = 1.0f;   // self loop contributes 1 to degree
}

// Convert/copy indices to int32 scratch + accumulate degree (dst side).
__global__ void k_prep_edges(const int* __restrict__ w, int E, int n) {
    int e = blockIdx.x * blockDim.x + threadIdx.x;
    if (e >= E) return;
    int s, d;
    if (g_fmt64) {
        s = w[2 * (size_t)e];                 // low word of int64
        d = w[2 * ((size_t)E + e)];
    } else {
        s = w[e];
        d = w[(size_t)E + e];
    }
    if ((unsigned)s >= (unsigned)n) s = 0;    // defensive clamp (no IMA)
    if ((unsigned)d >= (unsigned)n) d = 0;
    g_src[e] = s;
    g_dst[e] = d;
    atomicAdd(&g_dinv[d], 1.0f);              // REDG
}

__global__ void k_rsqrt(int n) {
    int i = blockIdx.x * blockDim.x + threadIdx.x;
    if (i < n) g_dinv[i] = rsqrtf(g_dinv[i]);   // deg >= 1 always
}

// ---------------------------------------------------------
// GEMM1: h1 = x @ W1  (n x 512) @ (512 x 16), thread-per-row, W1 in smem.
// Fused epilogue: agg1 = h1 * dinv^2 (self-loop init of layer-1 aggregation).
__global__ void k_gemm1(const float* __restrict__ x,
                        const float* __restrict__ W1, int n) {
    __shared__ float Ws[FIN * HID];   // 32 KB
    for (int i = threadIdx.x; i < FIN * HID; i += blockDim.x) Ws[i] = W1[i];
    __syncthreads();

    int row = blockIdx.x * blockDim.x + threadIdx.x;
    if (row >= n) return;

    float acc[HID];
#pragma unroll
    for (int j = 0; j < HID; j++) acc[j] = 0.0f;

    const float4* xr = reinterpret_cast<const float4*>(x) + (size_t)row * (FIN / 4);
#pragma unroll 4
    for (int k4 = 0; k4 < FIN / 4; k4++) {
        float4 xv = __ldg(xr + k4);
        const float* w0 = &Ws[k4 * 4 * HID];
#pragma unroll
        for (int j = 0; j < HID; j++) {
            float a = acc[j];
            a = fmaf(xv.x, w0[0 * HID + j], a);
            a = fmaf(xv.y, w0[1 * HID + j], a);
            a = fmaf(xv.z, w0[2 * HID + j], a);
            a = fmaf(xv.w, w0[3 * HID + j], a);
            acc[j] = a;
        }
    }

    float di = g_dinv[row];
    float d2 = di * di;
    float4* h = g_h1 + (size_t)row * (HID / 4);
    float4* a = g_agg1 + (size_t)row * (HID / 4);
#pragma unroll
    for (int q = 0; q < HID / 4; q++) {
        float4 v;
        v.x = acc[q * 4 + 0]; v.y = acc[q * 4 + 1];
        v.z = acc[q * 4 + 2]; v.w = acc[q * 4 + 3];
        h[q] = v;
        float4 va;
        va.x = v.x * d2; va.y = v.y * d2; va.z = v.z * d2; va.w = v.w * d2;
        a[q] = va;
    }
}

// ---------------------------------------------------------
// Vectorized global reduction (4 floats per op). Destination must be 16B aligned.
__device__ __forceinline__ void red_add_v4(float4* p, float a, float b, float c, float d) {
    asm volatile("red.global.add.v4.f32 [%0], {%1, %2, %3, %4};"
                 :: "l"(p), "f"(a), "f"(b), "f"(c), "f"(d)
                 : "memory");
}

// Edge scatter (used for BOTH layers): agg[dst] += h[src] * dinv[src]*dinv[dst]
// 16 features per edge = 4 vector reds. Norm computed in-flight (dinv is L2-hot).
__global__ void k_scatter16(int E) {
    int e = blockIdx.x * blockDim.x + threadIdx.x;
    if (e >= E) return;
    int s = g_src[e];
    int d = g_dst[e];
    float w = g_dinv[s] * g_dinv[d];

    const float4* fs = g_h1 + (size_t)s * (HID / 4);
    float4 v0 = __ldg(fs + 0);
    float4 v1 = __ldg(fs + 1);
    float4 v2 = __ldg(fs + 2);
    float4 v3 = __ldg(fs + 3);

    float4* ap = g_agg1 + (size_t)d * (HID / 4);
    red_add_v4(ap + 0, v0.x * w, v0.y * w, v0.z * w, v0.w * w);
    red_add_v4(ap + 1, v1.x * w, v1.y * w, v1.z * w, v1.w * w);
    red_add_v4(ap + 2, v2.x * w, v2.y * w, v2.z * w, v2.w * w);
    red_add_v4(ap + 3, v3.x * w, v3.y * w, v3.z * w, v3.w * w);
}

// ---------------------------------------------------------
// Mid: z = relu(agg1 + b1); store z into g_h1 (h1 is dead);
// re-seed g_agg1 = z * dinv^2 in-place (self-loop init of layer-2 aggregation).
__global__ void k_mid(const float* __restrict__ b1, int n) {
    int idx = blockIdx.x * blockDim.x + threadIdx.x;     // quad index
    int nq = n * (HID / 4);
    if (idx >= nq) return;
    int i = idx >> 2;                 // node
    int q = idx & 3;                  // which quad of the row
    float4 v = g_agg1[idx];
    const float* bq = b1 + q * 4;
    v.x = fmaxf(v.x + __ldg(bq + 0), 0.0f);
    v.y = fmaxf(v.y + __ldg(bq + 1), 0.0f);
    v.z = fmaxf(v.z + __ldg(bq + 2), 0.0f);
    v.w = fmaxf(v.w + __ldg(bq + 3), 0.0f);
    g_h1[idx] = v;
    float di = g_dinv[i];
    float d2 = di * di;
    float4 va;
    va.x = v.x * d2; va.y = v.y * d2; va.z = v.z * d2; va.w = v.w * d2;
    g_agg1[idx] = va;
}

// ---------------------------------------------------------
// Output: out[i][j] = sum_k agg2[i][k] * W2[k][j] + b2[j]
// (Reassociation: A @ (z @ W2) == (A @ z) @ W2, so the 16->40 GEMM happens
// AFTER aggregation — layer-2 scatter stays 16-wide.)
__global__ void k_out(const float* __restrict__ W2,
                      const float* __restrict__ b2,
                      float* __restrict__ out, int n) {
    __shared__ float W2s[HID * NCLS];   // 640 floats
    __shared__ float b2s[NCLS];
    for (int i = threadIdx.x; i < HID * NCLS; i += blockDim.x) W2s[i] = W2[i];
    for (int i = threadIdx.x; i < NCLS; i += blockDim.x) b2s[i] = b2[i];
    __syncthreads();

    int idx = blockIdx.x * blockDim.x + threadIdx.x;
    if (idx >= n * NCLS) return;
    int i = idx / NCLS;
    int j = idx - i * NCLS;

    const float4* a = g_agg1 + (size_t)i * (HID / 4);
    float4 a0 = a[0];
    float4 a1 = a[1];
    float4 a2 = a[2];
    float4 a3 = a[3];

    float acc = b2s[j];
    acc = fmaf(a0.x, W2s[0 * NCLS + j], acc);
    acc = fmaf(a0.y, W2s[1 * NCLS + j], acc);
    acc = fmaf(a0.z, W2s[2 * NCLS + j], acc);
    acc = fmaf(a0.w, W2s[3 * NCLS + j], acc);
    acc = fmaf(a1.x, W2s[4 * NCLS + j], acc);
    acc = fmaf(a1.y, W2s[5 * NCLS + j], acc);
    acc = fmaf(a1.z, W2s[6 * NCLS + j], acc);
    acc = fmaf(a1.w, W2s[7 * NCLS + j], acc);
    acc = fmaf(a2.x, W2s[8 * NCLS + j], acc);
    acc = fmaf(a2.y, W2s[9 * NCLS + j], acc);
    acc = fmaf(a2.z, W2s[10 * NCLS + j], acc);
    acc = fmaf(a2.w, W2s[11 * NCLS + j], acc);
    acc = fmaf(a3.x, W2s[12 * NCLS + j], acc);
    acc = fmaf(a3.y, W2s[13 * NCLS + j], acc);
    acc = fmaf(a3.z, W2s[14 * NCLS + j], acc);
    acc = fmaf(a3.w, W2s[15 * NCLS + j], acc);
    out[idx] = acc;
}

// ---------------------------------------------------------
extern "C" void kernel_launch(void* const* d_in, const int* in_sizes, int n_in,
                              void* d_out, int out_size) {
    // Identify inputs by unique element counts (ordering-robust):
    //   x: 100000*512 = 51,200,000   edge_index: 2*3,200,000 = 6,400,000
    //   W1: 512*16 = 8192            b1: 16
    //   W2: 16*40 = 640              b2: 40
    const float* x  = nullptr;
    const int*   ei = nullptr;
    const float* W1 = nullptr;
    const float* b1 = nullptr;
    const float* W2 = nullptr;
    const float* b2 = nullptr;
    for (int i = 0; i < n_in; i++) {
        switch (in_sizes[i]) {
            case 51200000: x  = (const float*)d_in[i]; break;
            case 6400000:  ei = (const int*)d_in[i];   break;
            case 8192:     W1 = (const float*)d_in[i]; break;
            case 16:       b1 = (const float*)d_in[i]; break;
            case 640:      W2 = (const float*)d_in[i]; break;
            case 40:       b2 = (const float*)d_in[i]; break;
            default: break;
        }
    }
    float* out = (float*)d_out;
    const int n = NMAX;
    const int E = EMAX;
    (void)out_size;

    k_detect_fmt<<<1, 1>>>((const unsigned int*)ei);
    k_init_deg<<<(n + 255) / 256, 256>>>(n);
    k_prep_edges<<<(E + 255) / 256, 256>>>(ei, E, n);
    k_rsqrt<<<(n + 255) / 256, 256>>>(n);
    k_gemm1<<<(n + 127) / 128, 128>>>(x, W1, n);
    k_scatter16<<<(E + 255) / 256, 256>>>(E);                    // layer-1 aggregation
    k_mid<<<(n * (HID / 4) + 255) / 256, 256>>>(b1, n);          // relu + re-seed
    k_scatter16<<<(E + 255) / 256, 256>>>(E);                    // layer-2 aggregation
    k_out<<<(n * NCLS + 255) / 256, 256>>>(W2, b2, out, n);      // 16->40 GEMM + b2
}

// round 6
// speedup vs baseline: 1.3167x; 1.3167x over previous
#include <cuda_runtime.h>

// Problem dims (fixed by the dataset): N=100000 nodes, F_in=512, HID=16,
// NCLS=40, E=3200000 directed edges (+N implicit self loops).
#define NMAX 100000
#define EMAX 3200000
#define FIN  512
#define HID  16
#define NCLS 40
#define SCAN_B 1024                          // nodes per scan block
#define NSB ((NMAX + SCAN_B - 1) / SCAN_B)   // 98 scan blocks

// -------- device scratch (~27 MB total; no allocations) -----------------
// NOTE: these symbols are ONLY referenced inside device code. Passing a
// __device__ array as a host-side kernel argument passes the host shadow
// address (bogus) — that was the rounds-4/5 failure.
__device__ float4 g_h[NMAX * HID / 4];   // gemm1 out; REUSED as layer-2 agg out
__device__ float4 g_z[NMAX * HID / 4];   // relu(agg1+b1) (layer-2 input)
__device__ float  g_dinv[NMAX];          // rsqrt(degree)
__device__ int    g_cnt[NMAX];           // in-degree / fill cursor
__device__ int    g_off[NMAX + 1];       // CSR row offsets
__device__ int    g_adj[EMAX];           // CSR adjacency (src ids), 12.8 MB
__device__ int    g_bsum[NSB];           // scan partials
__device__ int    g_fmt64;               // 1 if edge_index is int64 on device

// ---------------------------------------------------------
// Detect edge_index element width (int64 low/high words vs packed int32).
__global__ void k_detect_fmt(const unsigned int* __restrict__ w) {
    unsigned int acc = 0;
#pragma unroll
    for (int i = 0; i < 128; i++) acc |= w[2 * i + 1];
    g_fmt64 = (acc == 0u) ? 1 : 0;
}

__global__ void k_zero_cnt(int n) {
    int i = blockIdx.x * blockDim.x + threadIdx.x;
    if (i < n) g_cnt[i] = 0;
}

__device__ __forceinline__ void load_edge(const int* __restrict__ w, int e,
                                          int E, int n, int& s, int& d) {
    if (g_fmt64) {
        s = w[2 * (size_t)e];
        d = w[2 * ((size_t)E + e)];
    } else {
        s = w[e];
        d = w[(size_t)E + e];
    }
    if ((unsigned)s >= (unsigned)n) s = 0;
    if ((unsigned)d >= (unsigned)n) d = 0;
}

// Pass 1: in-degree histogram.
__global__ void k_count(const int* __restrict__ w, int E, int n) {
    int e = blockIdx.x * blockDim.x + threadIdx.x;
    if (e >= E) return;
    int s, d;
    load_edge(w, e, E, n, s, d);
    atomicAdd(&g_cnt[d], 1);
}

// Scan stage 1: per-block exclusive scan of g_cnt into g_off, block totals
// into g_bsum. Also computes dinv = rsqrt(deg+1) and zeroes g_cnt (cursor).
__global__ void k_scan1(int n) {
    __shared__ int sh[SCAN_B];
    int i = blockIdx.x * SCAN_B + threadIdx.x;
    int v = (i < n) ? g_cnt[i] : 0;
    if (i < n) {
        g_dinv[i] = rsqrtf((float)v + 1.0f);
        g_cnt[i] = 0;
    }
    sh[threadIdx.x] = v;
    __syncthreads();
    for (int off = 1; off < SCAN_B; off <<= 1) {
        int t = (threadIdx.x >= off) ? sh[threadIdx.x - off] : 0;
        __syncthreads();
        sh[threadIdx.x] += t;
        __syncthreads();
    }
    if (i < n) g_off[i] = sh[threadIdx.x] - v;   // exclusive
    if (threadIdx.x == SCAN_B - 1) g_bsum[blockIdx.x] = sh[SCAN_B - 1];
}

// Scan stage 2: single-thread exclusive scan of the 98 block sums.
__global__ void k_scan2(int E) {
    int run = 0;
    for (int b = 0; b < NSB; b++) {
        int t = g_bsum[b];
        g_bsum[b] = run;
        run += t;
    }
    g_off[NMAX] = E;
}

// Scan stage 3: add block offsets.
__global__ void k_scan3(int n) {
    int i = blockIdx.x * blockDim.x + threadIdx.x;
    if (i < n) g_off[i] += g_bsum[i / SCAN_B];
}

// Pass 2: fill CSR adjacency.
__global__ void k_fill(const int* __restrict__ w, int E, int n) {
    int e = blockIdx.x * blockDim.x + threadIdx.x;
    if (e >= E) return;
    int s, d;
    load_edge(w, e, E, n, s, d);
    int pos = atomicAdd(&g_cnt[d], 1);
    g_adj[g_off[d] + pos] = s;
}

// ---------------------------------------------------------
// GEMM1: h = x @ W1  (n x 512) @ (512 x 16), thread-per-row, W1 in smem.
__global__ void k_gemm1(const float* __restrict__ x,
                        const float* __restrict__ W1, int n) {
    __shared__ float Ws[FIN * HID];   // 32 KB
    for (int i = threadIdx.x; i < FIN * HID; i += blockDim.x) Ws[i] = W1[i];
    __syncthreads();

    int row = blockIdx.x * blockDim.x + threadIdx.x;
    if (row >= n) return;

    float acc[HID];
#pragma unroll
    for (int j = 0; j < HID; j++) acc[j] = 0.0f;

    const float4* xr = reinterpret_cast<const float4*>(x) + (size_t)row * (FIN / 4);
#pragma unroll 4
    for (int k4 = 0; k4 < FIN / 4; k4++) {
        float4 xv = __ldg(xr + k4);
        const float* w0 = &Ws[k4 * 4 * HID];
#pragma unroll
        for (int j = 0; j < HID; j++) {
            float a = acc[j];
            a = fmaf(xv.x, w0[0 * HID + j], a);
            a = fmaf(xv.y, w0[1 * HID + j], a);
            a = fmaf(xv.z, w0[2 * HID + j], a);
            a = fmaf(xv.w, w0[3 * HID + j], a);
            acc[j] = a;
        }
    }

    float4* h = g_h + (size_t)row * (HID / 4);
#pragma unroll
    for (int q = 0; q < HID / 4; q++) {
        float4 v;
        v.x = acc[q * 4 + 0]; v.y = acc[q * 4 + 1];
        v.z = acc[q * 4 + 2]; v.w = acc[q * 4 + 3];
        h[q] = v;
    }
}

// ---------------------------------------------------------
// Aggregation, one WARP per dst node, zero atomics, CSR neighbor list.
//   out_row(d) = dinv[d]^2 * in[d] + sum_e dinv[src_e]*dinv[d] * in[src_e]
// 8 groups of 4 lanes; each group handles one edge, each lane one float4
// quad. Tree-reduce across groups via shfl.
// LAYER=1: in=g_h, out=g_z, epilogue relu(agg+b1).
// LAYER=2: in=g_z, out=g_h, raw agg.
// Buffers are referenced directly in device code (never host-passed).
template <int LAYER>
__global__ void k_aggregate(const float* __restrict__ b1, int n) {
    const float4* in  = (LAYER == 1) ? g_h : g_z;
    float4*       out = (LAYER == 1) ? g_z : g_h;

    int gw = (blockIdx.x * blockDim.x + threadIdx.x) >> 5;   // node = warp id
    if (gw >= n) return;
    int lane = threadIdx.x & 31;
    int grp = lane >> 2;
    int q = lane & 3;

    int beg = g_off[gw];
    int end = g_off[gw + 1];
    float dd = g_dinv[gw];

    float4 acc = make_float4(0.f, 0.f, 0.f, 0.f);
    for (int i = beg + grp; i < end; i += 8) {
        int s = __ldg(g_adj + i);
        float w = __ldg(&g_dinv[s]) * dd;
        float4 v = __ldg(in + (size_t)s * (HID / 4) + q);
        acc.x = fmaf(w, v.x, acc.x);
        acc.y = fmaf(w, v.y, acc.y);
        acc.z = fmaf(w, v.z, acc.z);
        acc.w = fmaf(w, v.w, acc.w);
    }

#pragma unroll
    for (int off = 16; off >= 4; off >>= 1) {
        acc.x += __shfl_down_sync(0xffffffffu, acc.x, off);
        acc.y += __shfl_down_sync(0xffffffffu, acc.y, off);
        acc.z += __shfl_down_sync(0xffffffffu, acc.z, off);
        acc.w += __shfl_down_sync(0xffffffffu, acc.w, off);
    }

    if (lane < 4) {
        float4 v = __ldg(in + (size_t)gw * (HID / 4) + lane);   // self loop
        float ws = dd * dd;
        acc.x = fmaf(ws, v.x, acc.x);
        acc.y = fmaf(ws, v.y, acc.y);
        acc.z = fmaf(ws, v.z, acc.z);
        acc.w = fmaf(ws, v.w, acc.w);
        if (LAYER == 1) {
            const float4* b4 = reinterpret_cast<const float4*>(b1);
            float4 b = __ldg(b4 + lane);
            acc.x = fmaxf(acc.x + b.x, 0.f);
            acc.y = fmaxf(acc.y + b.y, 0.f);
            acc.z = fmaxf(acc.z + b.z, 0.f);
            acc.w = fmaxf(acc.w + b.w, 0.f);
        }
        out[(size_t)gw * (HID / 4) + lane] = acc;
    }
}

// ---------------------------------------------------------
// Output: out[i][j] = sum_k agg2[i][k] * W2[k][j] + b2[j]
// (Reassociation: A @ (z @ W2) == (A @ z) @ W2.)  agg2 lives in g_h (reused).
__global__ void k_out(const float* __restrict__ W2,
                      const float* __restrict__ b2,
                      float* __restrict__ out, int n) {
    __shared__ float W2s[HID * NCLS];
    __shared__ float b2s[NCLS];
    for (int i = threadIdx.x; i < HID * NCLS; i += blockDim.x) W2s[i] = W2[i];
    for (int i = threadIdx.x; i < NCLS; i += blockDim.x) b2s[i] = b2[i];
    __syncthreads();

    int idx = blockIdx.x * blockDim.x + threadIdx.x;
    if (idx >= n * NCLS) return;
    int i = idx / NCLS;
    int j = idx - i * NCLS;

    const float4* a = g_h + (size_t)i * (HID / 4);
    float4 a0 = a[0];
    float4 a1 = a[1];
    float4 a2 = a[2];
    float4 a3 = a[3];

    float acc = b2s[j];
    acc = fmaf(a0.x, W2s[0 * NCLS + j], acc);
    acc = fmaf(a0.y, W2s[1 * NCLS + j], acc);
    acc = fmaf(a0.z, W2s[2 * NCLS + j], acc);
    acc = fmaf(a0.w, W2s[3 * NCLS + j], acc);
    acc = fmaf(a1.x, W2s[4 * NCLS + j], acc);
    acc = fmaf(a1.y, W2s[5 * NCLS + j], acc);
    acc = fmaf(a1.z, W2s[6 * NCLS + j], acc);
    acc = fmaf(a1.w, W2s[7 * NCLS + j], acc);
    acc = fmaf(a2.x, W2s[8 * NCLS + j], acc);
    acc = fmaf(a2.y, W2s[9 * NCLS + j], acc);
    acc = fmaf(a2.z, W2s[10 * NCLS + j], acc);
    acc = fmaf(a2.w, W2s[11 * NCLS + j], acc);
    acc = fmaf(a3.x, W2s[12 * NCLS + j], acc);
    acc = fmaf(a3.y, W2s[13 * NCLS + j], acc);
    acc = fmaf(a3.z, W2s[14 * NCLS + j], acc);
    acc = fmaf(a3.w, W2s[15 * NCLS + j], acc);
    out[idx] = acc;
}

// ---------------------------------------------------------
extern "C" void kernel_launch(void* const* d_in, const int* in_sizes, int n_in,
                              void* d_out, int out_size) {
    // Identify inputs by unique element counts (ordering-robust).
    const float* x  = nullptr;
    const int*   ei = nullptr;
    const float* W1 = nullptr;
    const float* b1 = nullptr;
    const float* W2 = nullptr;
    const float* b2 = nullptr;
    for (int i = 0; i < n_in; i++) {
        switch (in_sizes[i]) {
            case 51200000: x  = (const float*)d_in[i]; break;
            case 6400000:  ei = (const int*)d_in[i];   break;
            case 8192:     W1 = (const float*)d_in[i]; break;
            case 16:       b1 = (const float*)d_in[i]; break;
            case 640:      W2 = (const float*)d_in[i]; break;
            case 40:       b2 = (const float*)d_in[i]; break;
            default: break;
        }
    }
    float* out = (float*)d_out;
    const int n = NMAX;
    const int E = EMAX;
    (void)out_size;

    k_detect_fmt<<<1, 1>>>((const unsigned int*)ei);
    k_zero_cnt<<<(n + 255) / 256, 256>>>(n);
    k_count<<<(E + 255) / 256, 256>>>(ei, E, n);
    k_scan1<<<NSB, SCAN_B>>>(n);
    k_scan2<<<1, 1>>>(E);
    k_scan3<<<(n + 255) / 256, 256>>>(n);
    k_fill<<<(E + 255) / 256, 256>>>(ei, E, n);

    k_gemm1<<<(n + 127) / 128, 128>>>(x, W1, n);

    int agg_blocks = (n * 32 + 255) / 256;                 // 1 warp / node
    k_aggregate<1><<<agg_blocks, 256>>>(b1, n);            // g_h -> g_z (+relu)
    k_aggregate<2><<<agg_blocks, 256>>>(b1, n);            // g_z -> g_h (raw)
    k_out<<<(n * NCLS + 255) / 256, 256>>>(W2, b2, out, n);
}

// round 7
// speedup vs baseline: 1.6092x; 1.2221x over previous
#include <cuda_runtime.h>

// Problem dims (fixed by the dataset): N=100000 nodes, F_in=512, HID=16,
// NCLS=40, E=3200000 directed edges (+N implicit self loops).
#define NMAX 100000
#define EMAX 3200000
#define FIN  512
#define HID  16
#define NCLS 40
#define SCAN_B 1024                          // nodes per scan block
#define NSB ((NMAX + SCAN_B - 1) / SCAN_B)   // 98 scan blocks

// gemm1 tiling
#define G1T 128            // threads per block
#define G1R 256            // rows per block (2 per thread)
#define G1C 32             // K columns per stage
#define G1_XS_STRIDE 33    // padded row stride (conflict-free scalar LDS)
#define G1_SMEM ((FIN * HID + G1R * G1_XS_STRIDE) * 4)   // 32KB W + 33.8KB x

// -------- device scratch (~27 MB total; no allocations) -----------------
// These symbols are ONLY referenced inside device code (host-passing a
// __device__ symbol passes the host shadow address — rounds-4/5 failure).
__device__ float4 g_h[NMAX * HID / 4];   // h' = (x@W1)*dinv ; layer-1 input
__device__ float4 g_z[NMAX * HID / 4];   // z' = relu(agg1+b1)*dinv ; layer-2 input
__device__ float  g_dinv[NMAX];          // rsqrt(degree)
__device__ int    g_cnt[NMAX];           // in-degree / fill cursor
__device__ int    g_off[NMAX + 1];       // CSR row offsets
__device__ int    g_adj[EMAX];           // CSR adjacency (src ids), 12.8 MB
__device__ int    g_bsum[NSB];           // scan partials
__device__ int    g_fmt64;               // 1 if edge_index is int64 on device

// ---------------------------------------------------------
__global__ void k_detect_fmt(const unsigned int* __restrict__ w) {
    unsigned int acc = 0;
#pragma unroll
    for (int i = 0; i < 128; i++) acc |= w[2 * i + 1];
    g_fmt64 = (acc == 0u) ? 1 : 0;
}

__global__ void k_zero_cnt(int n) {
    int i = blockIdx.x * blockDim.x + threadIdx.x;
    if (i < n) g_cnt[i] = 0;
}

__device__ __forceinline__ void load_edge(const int* __restrict__ w, int e,
                                          int E, int n, int& s, int& d) {
    if (g_fmt64) {
        s = w[2 * (size_t)e];
        d = w[2 * ((size_t)E + e)];
    } else {
        s = w[e];
        d = w[(size_t)E + e];
    }
    if ((unsigned)s >= (unsigned)n) s = 0;
    if ((unsigned)d >= (unsigned)n) d = 0;
}

__global__ void k_count(const int* __restrict__ w, int E, int n) {
    int e = blockIdx.x * blockDim.x + threadIdx.x;
    if (e >= E) return;
    int s, d;
    load_edge(w, e, E, n, s, d);
    atomicAdd(&g_cnt[d], 1);
}

// Per-block exclusive scan of g_cnt -> g_off; block totals -> g_bsum.
// Also computes dinv = rsqrt(deg+1) and zeroes g_cnt (fill cursor).
__global__ void k_scan1(int n) {
    __shared__ int sh[SCAN_B];
    int i = blockIdx.x * SCAN_B + threadIdx.x;
    int v = (i < n) ? g_cnt[i] : 0;
    if (i < n) {
        g_dinv[i] = rsqrtf((float)v + 1.0f);
        g_cnt[i] = 0;
    }
    sh[threadIdx.x] = v;
    __syncthreads();
    for (int off = 1; off < SCAN_B; off <<= 1) {
        int t = (threadIdx.x >= off) ? sh[threadIdx.x - off] : 0;
        __syncthreads();
        sh[threadIdx.x] += t;
        __syncthreads();
    }
    if (i < n) g_off[i] = sh[threadIdx.x] - v;   // exclusive
    if (threadIdx.x == SCAN_B - 1) g_bsum[blockIdx.x] = sh[SCAN_B - 1];
}

__global__ void k_scan2(int E) {
    int run = 0;
    for (int b = 0; b < NSB; b++) {
        int t = g_bsum[b];
        g_bsum[b] = run;
        run += t;
    }
    g_off[NMAX] = E;
}

__global__ void k_scan3(int n) {
    int i = blockIdx.x * blockDim.x + threadIdx.x;
    if (i < n) g_off[i] += g_bsum[i / SCAN_B];
}

__global__ void k_fill(const int* __restrict__ w, int E, int n) {
    int e = blockIdx.x * blockDim.x + threadIdx.x;
    if (e >= E) return;
    int s, d;
    load_edge(w, e, E, n, s, d);
    int pos = atomicAdd(&g_cnt[d], 1);
    g_adj[g_off[d] + pos] = s;
}

// ---------------------------------------------------------
// GEMM1 (coalesced): h' = (x @ W1) * dinv.
// Block = 128 threads / 256 rows / K-chunks of 32.
// x tiles staged to smem with coalesced LDG.128; compute reads are
// conflict-free scalar LDS (row stride 33); W reads are warp-broadcast.
__global__ void k_gemm1(const float* __restrict__ x,
                        const float* __restrict__ W1, int n) {
    extern __shared__ float sm[];
    float* Ws = sm;                      // FIN*HID floats (32 KB)
    float* xs = sm + FIN * HID;          // G1R * 33 floats

    int t = threadIdx.x;
    for (int i = t; i < FIN * HID; i += G1T) Ws[i] = W1[i];

    int rowbase = blockIdx.x * G1R;
    int r0 = rowbase + t;
    int r1 = rowbase + t + G1T;

    float acc0[HID], acc1[HID];
#pragma unroll
    for (int j = 0; j < HID; j++) { acc0[j] = 0.f; acc1[j] = 0.f; }

    const float4* x4 = reinterpret_cast<const float4*>(x);

    for (int c = 0; c < FIN / G1C; c++) {          // 16 chunks
        // stage 256 rows x 32 cols = 2048 float4; 16 per thread, coalesced
#pragma unroll
        for (int i = 0; i < 16; i++) {
            int f4 = t + G1T * i;
            int row = f4 >> 3;                     // 8 float4 per row-chunk
            int c4 = f4 & 7;
            int gr = rowbase + row;
            float4 v = make_float4(0.f, 0.f, 0.f, 0.f);
            if (gr < n) v = __ldg(&x4[(size_t)gr * (FIN / 4) + c * 8 + c4]);
            float* p = &xs[row * G1_XS_STRIDE + c4 * 4];
            p[0] = v.x; p[1] = v.y; p[2] = v.z; p[3] = v.w;
        }
        __syncthreads();                           // also covers Ws on c==0

        const float* wbase = &Ws[c * G1C * HID];
#pragma unroll 8
        for (int kk = 0; kk < G1C; kk++) {
            float xv0 = xs[t * G1_XS_STRIDE + kk];
            float xv1 = xs[(t + G1T) * G1_XS_STRIDE + kk];
            const float* w = wbase + kk * HID;
#pragma unroll
            for (int j = 0; j < HID; j++) {
                acc0[j] = fmaf(xv0, w[j], acc0[j]);
                acc1[j] = fmaf(xv1, w[j], acc1[j]);
            }
        }
        __syncthreads();
    }

    if (r0 < n) {
        float s = g_dinv[r0];
        float4* h = g_h + (size_t)r0 * (HID / 4);
#pragma unroll
        for (int q = 0; q < HID / 4; q++)
            h[q] = make_float4(acc0[q*4+0]*s, acc0[q*4+1]*s, acc0[q*4+2]*s, acc0[q*4+3]*s);
    }
    if (r1 < n) {
        float s = g_dinv[r1];
        float4* h = g_h + (size_t)r1 * (HID / 4);
#pragma unroll
        for (int q = 0; q < HID / 4; q++)
            h[q] = make_float4(acc1[q*4+0]*s, acc1[q*4+1]*s, acc1[q*4+2]*s, acc1[q*4+3]*s);
    }
}

// ---------------------------------------------------------
// Layer-1 aggregation, one WARP per dst node, zero atomics, CSR list.
// Inputs are pre-scaled (h' = h*dinv), so the hot loop is gather+add only:
//   z'[d] = relu( dinv[d] * (sum_e h'[src] + h'[d]) + b1 ) * dinv[d]
__global__ void k_agg1(const float* __restrict__ b1, int n) {
    int gw = (blockIdx.x * blockDim.x + threadIdx.x) >> 5;
    if (gw >= n) return;
    int lane = threadIdx.x & 31;
    int grp = lane >> 2;
    int q = lane & 3;

    int beg = g_off[gw];
    int end = g_off[gw + 1];

    float4 acc = make_float4(0.f, 0.f, 0.f, 0.f);
    for (int i = beg + grp; i < end; i += 8) {
        int s = __ldg(g_adj + i);
        float4 v = __ldg(g_h + (size_t)s * (HID / 4) + q);
        acc.x += v.x; acc.y += v.y; acc.z += v.z; acc.w += v.w;
    }
#pragma unroll
    for (int off = 16; off >= 4; off >>= 1) {
        acc.x += __shfl_down_sync(0xffffffffu, acc.x, off);
        acc.y += __shfl_down_sync(0xffffffffu, acc.y, off);
        acc.z += __shfl_down_sync(0xffffffffu, acc.z, off);
        acc.w += __shfl_down_sync(0xffffffffu, acc.w, off);
    }
    if (lane < 4) {
        float4 v = g_h[(size_t)gw * (HID / 4) + lane];     // self (h')
        acc.x += v.x; acc.y += v.y; acc.z += v.z; acc.w += v.w;
        float dd = g_dinv[gw];
        float4 b = reinterpret_cast<const float4*>(b1)[lane];
        float4 r;
        r.x = fmaxf(fmaf(dd, acc.x, b.x), 0.f) * dd;
        r.y = fmaxf(fmaf(dd, acc.y, b.y), 0.f) * dd;
        r.z = fmaxf(fmaf(dd, acc.z, b.z), 0.f) * dd;
        r.w = fmaxf(fmaf(dd, acc.w, b.w), 0.f) * dd;
        g_z[(size_t)gw * (HID / 4) + lane] = r;
    }
}

// ---------------------------------------------------------
// Layer-2 aggregation fused with the 16->40 output GEMM + b2.
//   agg2[d] = dinv[d] * (sum_e z'[src] + z'[d])
//   out[d][j] = b2[j] + sum_k agg2[d][k] * W2[k][j]
__global__ void k_agg2(const float* __restrict__ W2,
                       const float* __restrict__ b2,
                       float* __restrict__ out, int n) {
    __shared__ float W2s[HID * NCLS];
    __shared__ float b2s[NCLS];
    for (int i = threadIdx.x; i < HID * NCLS; i += blockDim.x) W2s[i] = W2[i];
    for (int i = threadIdx.x; i < NCLS; i += blockDim.x) b2s[i] = b2[i];
    __syncthreads();

    int gw = (blockIdx.x * blockDim.x + threadIdx.x) >> 5;
    if (gw >= n) return;
    int lane = threadIdx.x & 31;
    int grp = lane >> 2;
    int q = lane & 3;

    int beg = g_off[gw];
    int end = g_off[gw + 1];

    float4 acc = make_float4(0.f, 0.f, 0.f, 0.f);
    for (int i = beg + grp; i < end; i += 8) {
        int s = __ldg(g_adj + i);
        float4 v = __ldg(g_z + (size_t)s * (HID / 4) + q);
        acc.x += v.x; acc.y += v.y; acc.z += v.z; acc.w += v.w;
    }
#pragma unroll
    for (int off = 16; off >= 4; off >>= 1) {
        acc.x += __shfl_down_sync(0xffffffffu, acc.x, off);
        acc.y += __shfl_down_sync(0xffffffffu, acc.y, off);
        acc.z += __shfl_down_sync(0xffffffffu, acc.z, off);
        acc.w += __shfl_down_sync(0xffffffffu, acc.w, off);
    }
    if (lane < 4) {                                        // add self (z')
        float4 v = g_z[(size_t)gw * (HID / 4) + lane];
        acc.x += v.x; acc.y += v.y; acc.z += v.z; acc.w += v.w;
    }
    // broadcast the 16 summed values (held in lanes 0-3) to all lanes
    float a[HID];
#pragma unroll
    for (int Q = 0; Q < 4; Q++) {
        a[Q*4+0] = __shfl_sync(0xffffffffu, acc.x, Q);
        a[Q*4+1] = __shfl_sync(0xffffffffu, acc.y, Q);
        a[Q*4+2] = __shfl_sync(0xffffffffu, acc.z, Q);
        a[Q*4+3] = __shfl_sync(0xffffffffu, acc.w, Q);
    }
    float dd = g_dinv[gw];

    float s1 = 0.f;
#pragma unroll
    for (int k = 0; k < HID; k++) s1 = fmaf(a[k], W2s[k * NCLS + lane], s1);
    out[(size_t)gw * NCLS + lane] = fmaf(dd, s1, b2s[lane]);

    if (lane < NCLS - 32) {                                // remaining 8 cols
        float s2 = 0.f;
#pragma unroll
        for (int k = 0; k < HID; k++) s2 = fmaf(a[k], W2s[k * NCLS + 32 + lane], s2);
        out[(size_t)gw * NCLS + 32 + lane] = fmaf(dd, s2, b2s[32 + lane]);
    }
}

// ---------------------------------------------------------
extern "C" void kernel_launch(void* const* d_in, const int* in_sizes, int n_in,
                              void* d_out, int out_size) {
    // Identify inputs by unique element counts (ordering-robust).
    const float* x  = nullptr;
    const int*   ei = nullptr;
    const float* W1 = nullptr;
    const float* b1 = nullptr;
    const float* W2 = nullptr;
    const float* b2 = nullptr;
    for (int i = 0; i < n_in; i++) {
        switch (in_sizes[i]) {
            case 51200000: x  = (const float*)d_in[i]; break;
            case 6400000:  ei = (const int*)d_in[i];   break;
            case 8192:     W1 = (const float*)d_in[i]; break;
            case 16:       b1 = (const float*)d_in[i]; break;
            case 640:      W2 = (const float*)d_in[i]; break;
            case 40:       b2 = (const float*)d_in[i]; break;
            default: break;
        }
    }
    float* out = (float*)d_out;
    const int n = NMAX;
    const int E = EMAX;
    (void)out_size;

    static int g1_attr_set = 0;
    if (!g1_attr_set) {
        cudaFuncSetAttribute(k_gemm1, cudaFuncAttributeMaxDynamicSharedMemorySize,
                             G1_SMEM);
        g1_attr_set = 1;
    }

    // Launch order puts k_gemm1 at index 5 so ncu's -s 5 -c 1 captures it.
    k_detect_fmt<<<1, 1>>>((const unsigned int*)ei);              // 0
    k_zero_cnt<<<(n + 255) / 256, 256>>>(n);                      // 1
    k_count<<<(E + 255) / 256, 256>>>(ei, E, n);                  // 2
    k_scan1<<<NSB, SCAN_B>>>(n);                                  // 3 (dinv ready)
    k_scan2<<<1, 1>>>(E);                                         // 4
    k_gemm1<<<(n + G1R - 1) / G1R, G1T, G1_SMEM>>>(x, W1, n);     // 5
    k_scan3<<<(n + 255) / 256, 256>>>(n);                         // 6
    k_fill<<<(E + 255) / 256, 256>>>(ei, E, n);                   // 7

    int agg_blocks = (n * 32 + 255) / 256;                        // 1 warp / node
    k_agg1<<<agg_blocks, 256>>>(b1, n);                           // 8
    k_agg2<<<agg_blocks, 256>>>(W2, b2, out, n);                  // 9 (fused out)
}